// round 3
// baseline (speedup 1.0000x reference)
#include <cuda_runtime.h>
#include <cuda_fp16.h>

// ---------------- scratch (device globals; no allocation allowed) ----------
#define NMAX  100032
#define ECAP  1664000

__device__ __half g_h [NMAX * 64];   // GEMM output (pre-scaled by dis[row]), fp16
__device__ __half g_a [NMAX * 64];   // post-aggregation activations, fp16
__device__ float  g_dis[NMAX];
__device__ int    g_cnt[NMAX];
__device__ int    g_rptr[NMAX];
__device__ int    g_col[ECAP];
__device__ int    g_bsum[128];

// packed fp32x2 helpers (sm_103a; ptxas never auto-fuses these)
#define FFMA2(d, a, b) \
    asm("fma.rn.f32x2 %0, %1, %2, %0;" : "+l"(d) : "l"(a), "l"(b))
#define PACK_DUP(d, f) \
    asm("mov.b64 %0, {%1, %1};" : "=l"(d) : "r"(__float_as_uint(f)))
#define UNPACK2(lo, hi, p) \
    asm("mov.b64 {%0, %1}, %2;" : "=f"(lo), "=f"(hi) : "l"(p))

// ---------------- preprocessing kernels ------------------------------------

__global__ void k_hist(const int* __restrict__ dst, int E) {
    int e = blockIdx.x * 256 + threadIdx.x;
    if (e < E) atomicAdd(&g_cnt[dst[e]], 1);
}

// block-wide exclusive scan helper (blockDim.x == 1024)
__device__ __forceinline__ int blockscan_excl(int v, int* total) {
    __shared__ int ws[32];
    int lane = threadIdx.x & 31, wid = threadIdx.x >> 5;
    int s = v;
#pragma unroll
    for (int o = 1; o < 32; o <<= 1) {
        int t = __shfl_up_sync(0xffffffffu, s, o);
        if (lane >= o) s += t;
    }
    if (lane == 31) ws[wid] = s;
    __syncthreads();
    if (wid == 0) {
        int u = ws[lane];
#pragma unroll
        for (int o = 1; o < 32; o <<= 1) {
            int t = __shfl_up_sync(0xffffffffu, u, o);
            if (lane >= o) u += t;
        }
        ws[lane] = u;
    }
    __syncthreads();
    int incl = s + (wid ? ws[wid - 1] : 0);
    if (total) *total = ws[31];
    return incl - v;
}

__global__ void k_scan1(int n) {
    int i = blockIdx.x * 1024 + threadIdx.x;
    int v = (i < n) ? g_cnt[i] : 0;
    int tot;
    int ex = blockscan_excl(v, &tot);
    if (i < n) g_rptr[i] = ex;
    if (threadIdx.x == 0) g_bsum[blockIdx.x] = tot;
}

__global__ void k_scan2(int nb) {
    int i = threadIdx.x;
    int v = (i < nb) ? g_bsum[i] : 0;   // reads complete before writes (barrier inside scan)
    int ex = blockscan_excl(v, nullptr);
    if (i < nb) g_bsum[i] = ex;
}

// fused: rptr += carry; dis = rsqrt(deg+1)
__global__ void k_scan3dis(int n) {
    int i = blockIdx.x * 1024 + threadIdx.x;
    if (i < n) {
        g_rptr[i] += g_bsum[blockIdx.x];
        g_dis[i] = rsqrtf((float)(g_cnt[i] + 1));   // +1 self loop; always > 0
    }
}

// CSR fill: post-increment rowptr in place. After this, rptr[i] == inclusive
// scan, so row i spans [i ? rptr[i-1] : 0, rptr[i]).
__global__ void k_fill(const int* __restrict__ src, const int* __restrict__ dst, int E) {
    int e = blockIdx.x * 256 + threadIdx.x;
    if (e < E) {
        int d = dst[e];
        int p = atomicAdd(&g_rptr[d], 1);
        g_col[p] = src[e];
    }
}

// ---------------- GEMM: H[n,64] = (A[n,K] @ W[K,64]) * dis[row] -> fp16 -----
// Register-blocked 4 rows x 8 cols per thread; cols held as 4 f32x2 pairs,
// inner product via packed fma.rn.f32x2 (2 FMA per issued instruction).
// HALF_IN: A is fp16 from g_a (layer 2); else fp32 from Ain (layer 1).
template <int K, bool HALF_IN>
__global__ void __launch_bounds__(256) k_gemm(const float* __restrict__ Ain,
                                              const float* __restrict__ W, int n) {
    __shared__ __align__(16) float sW[K * 64];
    int tid = threadIdx.x;
    for (int i = tid; i < K * 16; i += 256)
        ((float4*)sW)[i] = ((const float4*)W)[i];
    __syncthreads();

    int cc = tid & 7;            // 8 col-chunks of 8
    int rg = tid >> 3;           // 32 row-groups of 4
    int row0 = blockIdx.x * 128 + rg * 4;

    unsigned long long acc2[4][4];
#pragma unroll
    for (int r = 0; r < 4; r++)
#pragma unroll
        for (int c = 0; c < 4; c++) acc2[r][c] = 0ull;

    bool ok[4];
#pragma unroll
    for (int r = 0; r < 4; r++) ok[r] = (row0 + r) < n;

    for (int k0 = 0; k0 < K; k0 += 8) {
        float a8[4][8];
#pragma unroll
        for (int r = 0; r < 4; r++) {
            if (HALF_IN) {
                uint4 u = ok[r] ? *(const uint4*)(g_a + (size_t)(row0 + r) * K + k0)
                                : make_uint4(0, 0, 0, 0);
                float2 f0 = __half22float2(*(__half2*)&u.x);
                float2 f1 = __half22float2(*(__half2*)&u.y);
                float2 f2 = __half22float2(*(__half2*)&u.z);
                float2 f3 = __half22float2(*(__half2*)&u.w);
                a8[r][0] = f0.x; a8[r][1] = f0.y; a8[r][2] = f1.x; a8[r][3] = f1.y;
                a8[r][4] = f2.x; a8[r][5] = f2.y; a8[r][6] = f3.x; a8[r][7] = f3.y;
            } else {
                float4 v0 = ok[r] ? *(const float4*)(Ain + (size_t)(row0 + r) * K + k0)
                                  : make_float4(0.f, 0.f, 0.f, 0.f);
                float4 v1 = ok[r] ? *(const float4*)(Ain + (size_t)(row0 + r) * K + k0 + 4)
                                  : make_float4(0.f, 0.f, 0.f, 0.f);
                a8[r][0] = v0.x; a8[r][1] = v0.y; a8[r][2] = v0.z; a8[r][3] = v0.w;
                a8[r][4] = v1.x; a8[r][5] = v1.y; a8[r][6] = v1.z; a8[r][7] = v1.w;
            }
        }
#pragma unroll
        for (int kk = 0; kk < 8; kk++) {
            // w pairs for 8 cols: two 16B LDS loads, each = two f32x2 pairs
            ulonglong2 wA = *(const ulonglong2*)(sW + (k0 + kk) * 64 + cc * 8);
            ulonglong2 wB = *(const ulonglong2*)(sW + (k0 + kk) * 64 + cc * 8 + 4);
#pragma unroll
            for (int r = 0; r < 4; r++) {
                unsigned long long av2;
                PACK_DUP(av2, a8[r][kk]);
                FFMA2(acc2[r][0], av2, wA.x);
                FFMA2(acc2[r][1], av2, wA.y);
                FFMA2(acc2[r][2], av2, wB.x);
                FFMA2(acc2[r][3], av2, wB.y);
            }
        }
    }

#pragma unroll
    for (int r = 0; r < 4; r++) {
        if (!ok[r]) continue;
        float d = g_dis[row0 + r];
        float lo[4], hi[4];
#pragma unroll
        for (int c = 0; c < 4; c++) UNPACK2(lo[c], hi[c], acc2[r][c]);
        uint4 o;
        __half2 h0 = __floats2half2_rn(lo[0] * d, hi[0] * d);
        __half2 h1 = __floats2half2_rn(lo[1] * d, hi[1] * d);
        __half2 h2 = __floats2half2_rn(lo[2] * d, hi[2] * d);
        __half2 h3 = __floats2half2_rn(lo[3] * d, hi[3] * d);
        o.x = *(unsigned*)&h0; o.y = *(unsigned*)&h1;
        o.z = *(unsigned*)&h2; o.w = *(unsigned*)&h3;
        *(uint4*)(g_h + (size_t)(row0 + r) * 64 + cc * 8) = o;
    }
}

// ---------------- aggregation: warp per dst node ---------------------------
// out[i] = relu( dis[i] * (h'[i] + sum_{src in nbrs} h'[src]) + bias )
// h' rows are fp16 (128B/row, one half2 per lane). Accumulate fp32.
// Column indices fetched 4-at-a-time via one broadcast LDG.128.
// FC=true additionally applies the 64->4 FC + bfc and writes float4 per node.
template <bool FC>
__global__ void __launch_bounds__(256) k_agg(const float* __restrict__ bias,
                                             const float* __restrict__ Wfc,
                                             const float* __restrict__ bfc,
                                             float* __restrict__ out, int n) {
    int w = (blockIdx.x * 256 + threadIdx.x) >> 5;
    int lane = threadIdx.x & 31;
    if (w >= n) return;

    int start = w ? __ldg(&g_rptr[w - 1]) : 0;
    int end = __ldg(&g_rptr[w]);

    const __half2* __restrict__ H2 = (const __half2*)g_h;
    float2 acc = __half22float2(H2[(size_t)w * 32 + lane]);   // self loop

    int e = start;
    // peel to 4-alignment so the main loop can use one int4 load per 4 edges
    while (e < end && (e & 3)) {
        float2 v = __half22float2(H2[(size_t)__ldg(&g_col[e]) * 32 + lane]);
        acc.x += v.x; acc.y += v.y;
        e++;
    }
    for (; e + 4 <= end; e += 4) {
        int4 cs = *(const int4*)(g_col + e);   // broadcast LDG.128
        float2 v0 = __half22float2(H2[(size_t)cs.x * 32 + lane]);
        float2 v1 = __half22float2(H2[(size_t)cs.y * 32 + lane]);
        float2 v2 = __half22float2(H2[(size_t)cs.z * 32 + lane]);
        float2 v3 = __half22float2(H2[(size_t)cs.w * 32 + lane]);
        acc.x += (v0.x + v1.x) + (v2.x + v3.x);
        acc.y += (v0.y + v1.y) + (v2.y + v3.y);
    }
    while (e < end) {
        float2 v = __half22float2(H2[(size_t)__ldg(&g_col[e]) * 32 + lane]);
        acc.x += v.x; acc.y += v.y;
        e++;
    }

    float d = g_dis[w];
    float2 b = ((const float2*)bias)[lane];
    float ox = fmaxf(fmaf(acc.x, d, b.x), 0.f);
    float oy = fmaxf(fmaf(acc.y, d, b.y), 0.f);

    if (!FC) {
        ((__half2*)g_a)[(size_t)w * 32 + lane] = __floats2half2_rn(ox, oy);
    } else {
        const float4* Wf = (const float4*)Wfc;   // [64][4]
        float4 w0 = Wf[2 * lane], w1 = Wf[2 * lane + 1];
        float4 y;
        y.x = ox * w0.x + oy * w1.x;
        y.y = ox * w0.y + oy * w1.y;
        y.z = ox * w0.z + oy * w1.z;
        y.w = ox * w0.w + oy * w1.w;
#pragma unroll
        for (int o = 16; o; o >>= 1) {
            y.x += __shfl_xor_sync(0xffffffffu, y.x, o);
            y.y += __shfl_xor_sync(0xffffffffu, y.y, o);
            y.z += __shfl_xor_sync(0xffffffffu, y.z, o);
            y.w += __shfl_xor_sync(0xffffffffu, y.w, o);
        }
        if (lane == 0) {
            float4 bf = *(const float4*)bfc;
            ((float4*)out)[w] = make_float4(y.x + bf.x, y.y + bf.y, y.z + bf.z, y.w + bf.w);
        }
    }
}

// ---------------- launch ----------------------------------------------------

extern "C" void kernel_launch(void* const* d_in, const int* in_sizes, int n_in,
                              void* d_out, int out_size) {
    const float* x   = (const float*)d_in[0];
    const int*   ei  = (const int*)d_in[1];
    const float* W1  = (const float*)d_in[2];
    const float* b1  = (const float*)d_in[3];
    const float* W2  = (const float*)d_in[4];
    const float* b2  = (const float*)d_in[5];
    const float* Wfc = (const float*)d_in[6];
    const float* bfc = (const float*)d_in[7];

    int n = in_sizes[0] / 128;
    int E = in_sizes[1] / 2;
    if (n > NMAX) n = NMAX;
    if (E > ECAP) E = ECAP;
    const int* src = ei;
    const int* dst = ei + E;
    int nb = (n + 1023) / 1024;

    void* cnt_ptr = nullptr;
    cudaGetSymbolAddress(&cnt_ptr, g_cnt);
    cudaMemsetAsync(cnt_ptr, 0, (size_t)n * sizeof(int));

    k_hist<<<(E + 255) / 256, 256>>>(dst, E);
    k_scan1<<<nb, 1024>>>(n);
    k_scan2<<<1, 1024>>>(nb);
    k_scan3dis<<<nb, 1024>>>(n);
    k_fill<<<(E + 255) / 256, 256>>>(src, dst, E);

    k_gemm<128, false><<<(n + 127) / 128, 256>>>(x, W1, n);
    k_agg<false><<<(n + 7) / 8, 256>>>(b1, nullptr, nullptr, nullptr, n);
    k_gemm<64, true><<<(n + 127) / 128, 256>>>(nullptr, W2, n);
    k_agg<true><<<(n + 7) / 8, 256>>>(b2, Wfc, bfc, (float*)d_out, n);
}